// round 2
// baseline (speedup 1.0000x reference)
#include <cuda_runtime.h>
#include <math.h>

// ---------------- problem constants ----------------
#define NJ 30000
#define NS 12000
#define EJS 300000
#define ESJ 300000
#define ESS 150000
#define ESS_TOT (ESS + NS)   // + self loops
#define SB 384
#define HD 128
#define HH 256               // H * HID
#define NEG 0.2f

// ---------------- scratch (static device globals; no allocs) ----------------
__device__ float g_xj0[NJ * HD];
__device__ float g_xj1[NJ * HD];
__device__ float g_xs0[NS * HD];
__device__ float g_xs1[NS * HD];
__device__ float g_hsJ[NJ * HH];
__device__ float g_hsS[NS * HH];
__device__ float g_oJ[NJ * HH];
__device__ float g_oS[NS * HH];
__device__ float g_asb[NJ * 2];
__device__ float g_adb[NJ * 2];
__device__ float g_ebuf[EJS * 2];
__device__ float g_wbuf[EJS * 2];
__device__ float g_vd[6 * HD * 2];

__device__ int g_deg_js[NS], g_off_js[NS], g_cur_js[NS], g_list_js[EJS];
__device__ int g_deg_sj[NJ], g_off_sj[NJ], g_cur_sj[NJ], g_list_sj[ESJ];
__device__ int g_deg_ss[NS], g_off_ss[NS], g_cur_ss[NS], g_list_ss[ESS_TOT];

// ---------------- kernels ----------------

// y = relu(LN(x @ W + b) * g + be), x:[N,384] W:[384,128]
__global__ void k_lin0(const float* __restrict__ x, const float* __restrict__ W,
                       const float* __restrict__ b, const float* __restrict__ g,
                       const float* __restrict__ be, float* __restrict__ y) {
    __shared__ float sx[8][SB];
    __shared__ float red[4][8][2];
    int c = threadIdx.x;
    int n0 = blockIdx.x * 8;
    #pragma unroll
    for (int r = 0; r < 8; r++)
        for (int k = c; k < SB; k += 128)
            sx[r][k] = x[(n0 + r) * SB + k];
    __syncthreads();
    float acc[8];
    #pragma unroll
    for (int r = 0; r < 8; r++) acc[r] = b[c];
    for (int k = 0; k < SB; k++) {
        float w = W[k * HD + c];
        #pragma unroll
        for (int r = 0; r < 8; r++) acc[r] += sx[r][k] * w;
    }
    int lane = c & 31, wp = c >> 5;
    #pragma unroll
    for (int r = 0; r < 8; r++) {
        float s = acc[r], s2 = acc[r] * acc[r];
        #pragma unroll
        for (int o = 16; o; o >>= 1) {
            s  += __shfl_xor_sync(0xFFFFFFFFu, s, o);
            s2 += __shfl_xor_sync(0xFFFFFFFFu, s2, o);
        }
        if (lane == 0) { red[wp][r][0] = s; red[wp][r][1] = s2; }
    }
    __syncthreads();
    float gc = g[c], bec = be[c];
    #pragma unroll
    for (int r = 0; r < 8; r++) {
        float s  = red[0][r][0] + red[1][r][0] + red[2][r][0] + red[3][r][0];
        float s2 = red[0][r][1] + red[1][r][1] + red[2][r][1] + red[3][r][1];
        float mu = s * (1.0f / HD);
        float var = s2 * (1.0f / HD) - mu * mu;
        float rs = rsqrtf(var + 1e-5f);
        float v = (acc[r] - mu) * rs * gc + bec;
        y[(n0 + r) * HD + c] = fmaxf(v, 0.0f);
    }
}

// hs = x @ Ws (no bias), + alpha_s[n,h] = sum_c hs[n,h,c]*a[h,c]
__global__ void k_gat_src(const float* __restrict__ x, const float* __restrict__ W,
                          const float* __restrict__ avec, float* __restrict__ hs,
                          float* __restrict__ alpha) {
    __shared__ float sx[8][HD];
    __shared__ float red[8][8];
    int c = threadIdx.x;
    int n0 = blockIdx.x * 8;
    for (int i = c; i < 8 * HD; i += 256) {
        int r = i >> 7, k = i & 127;
        sx[r][k] = x[(n0 + r) * HD + k];
    }
    __syncthreads();
    float acc[8];
    #pragma unroll
    for (int r = 0; r < 8; r++) acc[r] = 0.0f;
    for (int k = 0; k < HD; k++) {
        float w = W[k * HH + c];
        #pragma unroll
        for (int r = 0; r < 8; r++) acc[r] += sx[r][k] * w;
    }
    #pragma unroll
    for (int r = 0; r < 8; r++) hs[(n0 + r) * HH + c] = acc[r];
    int h = c >> 7, cc = c & 127;
    float av = avec[h * HD + cc];
    int lane = c & 31, wp = c >> 5;
    #pragma unroll
    for (int r = 0; r < 8; r++) {
        float p = acc[r] * av;
        #pragma unroll
        for (int o = 16; o; o >>= 1) p += __shfl_xor_sync(0xFFFFFFFFu, p, o);
        if (lane == 0) red[wp][r] = p;
    }
    __syncthreads();
    if (c == 0) {
        #pragma unroll
        for (int r = 0; r < 8; r++)
            alpha[(n0 + r) * 2 + 0] = red[0][r] + red[1][r] + red[2][r] + red[3][r];
    }
    if (c == 128) {
        #pragma unroll
        for (int r = 0; r < 8; r++)
            alpha[(n0 + r) * 2 + 1] = red[4][r] + red[5][r] + red[6][r] + red[7][r];
    }
}

// alpha_d[n,h] = x[n,:] @ vd[:,h]   (vd = Wd @ a_d per head, precomputed)
__global__ void k_alpha_d(const float* __restrict__ x, const float* __restrict__ vd,
                          float* __restrict__ ad, int N) {
    int wp = threadIdx.x >> 5, lane = threadIdx.x & 31;
    int row = blockIdx.x * 8 + wp;
    if (row >= N) return;
    float a0 = 0.0f, a1 = 0.0f;
    for (int k = lane; k < HD; k += 32) {
        float xv = x[row * HD + k];
        a0 += xv * vd[k * 2 + 0];
        a1 += xv * vd[k * 2 + 1];
    }
    #pragma unroll
    for (int o = 16; o; o >>= 1) {
        a0 += __shfl_xor_sync(0xFFFFFFFFu, a0, o);
        a1 += __shfl_xor_sync(0xFFFFFFFFu, a1, o);
    }
    if (lane == 0) { ad[row * 2 + 0] = a0; ad[row * 2 + 1] = a1; }
}

// vd[lr][k][h] = sum_c Wd[lr][k][h*128+c] * a_d[lr][h][c]
__global__ void k_prep(const float* __restrict__ Wd, const float* __restrict__ adv,
                       float* __restrict__ vd) {
    int lr = blockIdx.x;
    int k = threadIdx.x >> 1, h = threadIdx.x & 1;
    const float* wrow = Wd + ((size_t)lr * HD + k) * HH + h * HD;
    const float* arow = adv + (lr * 2 + h) * HD;
    float s = 0.0f;
    for (int c = 0; c < HD; c++) s += wrow[c] * arow[c];
    vd[lr * (HD * 2) + k * 2 + h] = s;
}

__global__ void k_count(const int* __restrict__ dst, int E, int nReal,
                        int* __restrict__ deg) {
    int e = blockIdx.x * blockDim.x + threadIdx.x;
    if (e >= E) return;
    int d = (e < nReal) ? dst[e] : (e - nReal);
    atomicAdd(&deg[d], 1);
}

// 3 independent exclusive scans (one per block)
__global__ void k_scan3(const int* d0, int* o0, int n0,
                        const int* d1, int* o1, int n1,
                        const int* d2, int* o2, int n2) {
    const int* deg = (blockIdx.x == 0) ? d0 : (blockIdx.x == 1) ? d1 : d2;
    int* offs      = (blockIdx.x == 0) ? o0 : (blockIdx.x == 1) ? o1 : o2;
    int n          = (blockIdx.x == 0) ? n0 : (blockIdx.x == 1) ? n1 : n2;
    __shared__ int carry;
    __shared__ int buf[1024];
    int tid = threadIdx.x;
    if (tid == 0) carry = 0;
    __syncthreads();
    for (int base = 0; base < n; base += 1024) {
        int i = base + tid;
        int v = (i < n) ? deg[i] : 0;
        buf[tid] = v;
        __syncthreads();
        for (int off = 1; off < 1024; off <<= 1) {
            int t = (tid >= off) ? buf[tid - off] : 0;
            __syncthreads();
            buf[tid] += t;
            __syncthreads();
        }
        int incl = buf[tid];
        int cbase = carry;
        if (i < n) offs[i] = cbase + incl - v;
        __syncthreads();
        if (tid == 0) carry = cbase + buf[1023];
        __syncthreads();
    }
}

__global__ void k_scatter(const int* __restrict__ dst, int E, int nReal,
                          int* __restrict__ cur, int* __restrict__ list) {
    int e = blockIdx.x * blockDim.x + threadIdx.x;
    if (e >= E) return;
    int d = (e < nReal) ? dst[e] : (e - nReal);
    int pos = atomicAdd(&cur[d], 1);
    list[pos] = e;
}

// e[edge,h] = leaky_relu(alpha_s[src,h] + alpha_d[dst,h])
__global__ void k_edge(const int* __restrict__ src, const int* __restrict__ dst,
                       int E, int nReal, const float* __restrict__ as,
                       const float* __restrict__ ad, float* __restrict__ ebuf) {
    int e = blockIdx.x * blockDim.x + threadIdx.x;
    if (e >= E) return;
    int s, d;
    if (e < nReal) { s = src[e]; d = dst[e]; } else { s = d = e - nReal; }
    #pragma unroll
    for (int h = 0; h < 2; h++) {
        float v = as[s * 2 + h] + ad[d * 2 + h];
        ebuf[e * 2 + h] = (v > 0.0f) ? v : NEG * v;
    }
}

// per-dst softmax + weighted message sum. one block (256 thr) per dst node.
__global__ void k_agg(const int* __restrict__ deg, const int* __restrict__ off,
                      const int* __restrict__ list, const int* __restrict__ srcArr,
                      int nReal, const float* __restrict__ ebuf, float* __restrict__ wbuf,
                      const float* __restrict__ hs, const float* __restrict__ bias,
                      float* __restrict__ out, int accum) {
    __shared__ float sinv[2];
    int d = blockIdx.x;
    int dg = deg[d];
    int st = off[d];
    int tid = threadIdx.x, lane = tid & 31, wp = tid >> 5;
    if (wp < 2) {
        int h = wp;
        float m = -INFINITY;
        for (int i = lane; i < dg; i += 32) {
            int e = list[st + i];
            m = fmaxf(m, ebuf[e * 2 + h]);
        }
        #pragma unroll
        for (int o = 16; o; o >>= 1) m = fmaxf(m, __shfl_xor_sync(0xFFFFFFFFu, m, o));
        float den = 0.0f;
        for (int i = lane; i < dg; i += 32) {
            int e = list[st + i];
            float t = __expf(ebuf[e * 2 + h] - m);
            wbuf[e * 2 + h] = t;
            den += t;
        }
        #pragma unroll
        for (int o = 16; o; o >>= 1) den += __shfl_xor_sync(0xFFFFFFFFu, den, o);
        if (lane == 0) sinv[h] = 1.0f / (den + 1e-16f);
    }
    __syncthreads();
    int h = tid >> 7;
    float acc = 0.0f;
    for (int i = 0; i < dg; i++) {
        int e = list[st + i];
        int s = (e < nReal) ? srcArr[e] : (e - nReal);
        acc += wbuf[e * 2 + h] * hs[(size_t)s * HH + tid];
    }
    float o = acc * sinv[h] + bias[tid];
    size_t oi = (size_t)d * HH + tid;
    if (accum) out[oi] += o; else out[oi] = o;
}

// y = relu(x @ W + b), x:[N,256] W:[256,128]
__global__ void k_inter(const float* __restrict__ x, const float* __restrict__ W,
                        const float* __restrict__ b, float* __restrict__ y) {
    __shared__ float sx[8][HH];
    int c = threadIdx.x;
    int n0 = blockIdx.x * 8;
    for (int i = c; i < 8 * HH; i += 128) {
        int r = i >> 8, k = i & 255;
        sx[r][k] = x[(size_t)(n0 + r) * HH + k];
    }
    __syncthreads();
    float acc[8];
    #pragma unroll
    for (int r = 0; r < 8; r++) acc[r] = b[c];
    for (int k = 0; k < HH; k++) {
        float w = W[k * HD + c];
        #pragma unroll
        for (int r = 0; r < 8; r++) acc[r] += sx[r][k] * w;
    }
    #pragma unroll
    for (int r = 0; r < 8; r++) y[(n0 + r) * HD + c] = fmaxf(acc[r], 0.0f);
}

// q = query @ Wq + bq
__global__ void k_q(const float* __restrict__ query, const float* __restrict__ Wq,
                    const float* __restrict__ bq, float* __restrict__ q) {
    int c = threadIdx.x;
    float acc = bq[c];
    for (int k = 0; k < SB; k++) acc += query[k] * Wq[k * HD + c];
    q[c] = acc;
}

// emb = xj @ Wjf + bjf ; scores = emb @ q
__global__ void k_final(const float* __restrict__ xj, const float* __restrict__ W,
                        const float* __restrict__ b, const float* __restrict__ q,
                        float* __restrict__ scores, float* __restrict__ emb) {
    __shared__ float sx[8][HD];
    __shared__ float red[4][8];
    int c = threadIdx.x;
    int n0 = blockIdx.x * 8;
    for (int i = c; i < 8 * HD; i += 128) {
        int r = i >> 7, k = i & 127;
        sx[r][k] = xj[(n0 + r) * HD + k];
    }
    __syncthreads();
    float acc[8];
    #pragma unroll
    for (int r = 0; r < 8; r++) acc[r] = b[c];
    for (int k = 0; k < HD; k++) {
        float w = W[k * HD + c];
        #pragma unroll
        for (int r = 0; r < 8; r++) acc[r] += sx[r][k] * w;
    }
    float qv = q[c];
    int lane = c & 31, wp = c >> 5;
    #pragma unroll
    for (int r = 0; r < 8; r++) {
        emb[(size_t)(n0 + r) * HD + c] = acc[r];
        float p = acc[r] * qv;
        #pragma unroll
        for (int o = 16; o; o >>= 1) p += __shfl_xor_sync(0xFFFFFFFFu, p, o);
        if (lane == 0) red[wp][r] = p;
    }
    __syncthreads();
    if (c < 8) scores[n0 + c] = red[0][c] + red[1][c] + red[2][c] + red[3][c];
}

// ---------------- host launch ----------------
static inline int cdiv(int a, int b) { return (a + b - 1) / b; }

extern "C" void kernel_launch(void* const* d_in, const int* in_sizes, int n_in,
                              void* d_out, int out_size) {
    const float* x_job   = (const float*)d_in[0];
    const float* x_skill = (const float*)d_in[1];
    const int* js_src = (const int*)d_in[2];
    const int* js_dst = (const int*)d_in[3];
    const int* sj_src = (const int*)d_in[4];
    const int* sj_dst = (const int*)d_in[5];
    const int* ss_src = (const int*)d_in[6];
    const int* ss_dst = (const int*)d_in[7];
    const float* query    = (const float*)d_in[8];
    const float* W0_job   = (const float*)d_in[9];
    const float* b0_job   = (const float*)d_in[10];
    const float* g0_job   = (const float*)d_in[11];
    const float* be0_job  = (const float*)d_in[12];
    const float* W0_skill = (const float*)d_in[13];
    const float* b0_skill = (const float*)d_in[14];
    const float* g0_skill = (const float*)d_in[15];
    const float* be0_skill= (const float*)d_in[16];
    const float* gat_Ws = (const float*)d_in[17];
    const float* gat_Wd = (const float*)d_in[18];
    const float* gat_as = (const float*)d_in[19];
    const float* gat_ad = (const float*)d_in[20];
    const float* gat_b  = (const float*)d_in[21];
    const float* inter_W= (const float*)d_in[22];
    const float* inter_b= (const float*)d_in[23];
    const float* Wjf = (const float*)d_in[24];
    const float* bjf = (const float*)d_in[25];
    const float* Wq  = (const float*)d_in[26];
    const float* bq  = (const float*)d_in[27];

    float* out = (float*)d_out;
    float* out_scores = out;
    float* out_emb = out + NJ;
    float* out_q = out + NJ + (size_t)NJ * HD;

    // symbol addresses
    float *xj0, *xj1, *xs0, *xs1, *hsJ, *hsS, *oJ, *oS, *asb, *adb, *ebuf, *wbuf, *vd;
    int *deg_js, *off_js, *cur_js, *list_js;
    int *deg_sj, *off_sj, *cur_sj, *list_sj;
    int *deg_ss, *off_ss, *cur_ss, *list_ss;
    cudaGetSymbolAddress((void**)&xj0, g_xj0);
    cudaGetSymbolAddress((void**)&xj1, g_xj1);
    cudaGetSymbolAddress((void**)&xs0, g_xs0);
    cudaGetSymbolAddress((void**)&xs1, g_xs1);
    cudaGetSymbolAddress((void**)&hsJ, g_hsJ);
    cudaGetSymbolAddress((void**)&hsS, g_hsS);
    cudaGetSymbolAddress((void**)&oJ, g_oJ);
    cudaGetSymbolAddress((void**)&oS, g_oS);
    cudaGetSymbolAddress((void**)&asb, g_asb);
    cudaGetSymbolAddress((void**)&adb, g_adb);
    cudaGetSymbolAddress((void**)&ebuf, g_ebuf);
    cudaGetSymbolAddress((void**)&wbuf, g_wbuf);
    cudaGetSymbolAddress((void**)&vd, g_vd);
    cudaGetSymbolAddress((void**)&deg_js, g_deg_js);
    cudaGetSymbolAddress((void**)&off_js, g_off_js);
    cudaGetSymbolAddress((void**)&cur_js, g_cur_js);
    cudaGetSymbolAddress((void**)&list_js, g_list_js);
    cudaGetSymbolAddress((void**)&deg_sj, g_deg_sj);
    cudaGetSymbolAddress((void**)&off_sj, g_off_sj);
    cudaGetSymbolAddress((void**)&cur_sj, g_cur_sj);
    cudaGetSymbolAddress((void**)&list_sj, g_list_sj);
    cudaGetSymbolAddress((void**)&deg_ss, g_deg_ss);
    cudaGetSymbolAddress((void**)&off_ss, g_off_ss);
    cudaGetSymbolAddress((void**)&cur_ss, g_cur_ss);
    cudaGetSymbolAddress((void**)&list_ss, g_list_ss);

    // --- CSR build (per launch; edges are static inputs) ---
    cudaMemsetAsync(deg_js, 0, NS * sizeof(int));
    cudaMemsetAsync(deg_sj, 0, NJ * sizeof(int));
    cudaMemsetAsync(deg_ss, 0, NS * sizeof(int));
    k_count<<<cdiv(EJS, 256), 256>>>(js_dst, EJS, EJS, deg_js);
    k_count<<<cdiv(ESJ, 256), 256>>>(sj_dst, ESJ, ESJ, deg_sj);
    k_count<<<cdiv(ESS_TOT, 256), 256>>>(ss_dst, ESS_TOT, ESS, deg_ss);
    k_scan3<<<3, 1024>>>(deg_js, off_js, NS, deg_sj, off_sj, NJ, deg_ss, off_ss, NS);
    cudaMemcpyAsync(cur_js, off_js, NS * sizeof(int), cudaMemcpyDeviceToDevice);
    cudaMemcpyAsync(cur_sj, off_sj, NJ * sizeof(int), cudaMemcpyDeviceToDevice);
    cudaMemcpyAsync(cur_ss, off_ss, NS * sizeof(int), cudaMemcpyDeviceToDevice);
    k_scatter<<<cdiv(EJS, 256), 256>>>(js_dst, EJS, EJS, cur_js, list_js);
    k_scatter<<<cdiv(ESJ, 256), 256>>>(sj_dst, ESJ, ESJ, cur_sj, list_sj);
    k_scatter<<<cdiv(ESS_TOT, 256), 256>>>(ss_dst, ESS_TOT, ESS, cur_ss, list_ss);

    // --- init linears + LN + relu ---
    k_lin0<<<NJ / 8, 128>>>(x_job, W0_job, b0_job, g0_job, be0_job, xj0);
    k_lin0<<<NS / 8, 128>>>(x_skill, W0_skill, b0_skill, g0_skill, be0_skill, xs0);
    k_prep<<<6, 256>>>(gat_Wd, gat_ad, vd);

    float* xj_cur = xj0; float* xs_cur = xs0;
    float* xj_nxt = xj1; float* xs_nxt = xs1;

    for (int l = 0; l < 2; l++) {
        // relation js (lr = l*3+0): jobs -> skills, output into oS (init)
        {
            int lr = l * 3 + 0;
            k_gat_src<<<NJ / 8, 256>>>(xj_cur, gat_Ws + (size_t)lr * HD * HH,
                                       gat_as + lr * 2 * HD, hsJ, asb);
            k_alpha_d<<<cdiv(NS, 8), 256>>>(xs_cur, vd + lr * HD * 2, adb, NS);
            k_edge<<<cdiv(EJS, 256), 256>>>(js_src, js_dst, EJS, EJS, asb, adb, ebuf);
            k_agg<<<NS, 256>>>(deg_js, off_js, list_js, js_src, EJS, ebuf, wbuf,
                               hsJ, gat_b + lr * HH, oS, 0);
        }
        // relation ss (lr = l*3+2): skills -> skills (+self loops), accumulate into oS
        {
            int lr = l * 3 + 2;
            k_gat_src<<<NS / 8, 256>>>(xs_cur, gat_Ws + (size_t)lr * HD * HH,
                                       gat_as + lr * 2 * HD, hsS, asb);
            k_alpha_d<<<cdiv(NS, 8), 256>>>(xs_cur, vd + lr * HD * 2, adb, NS);
            k_edge<<<cdiv(ESS_TOT, 256), 256>>>(ss_src, ss_dst, ESS_TOT, ESS, asb, adb, ebuf);
            k_agg<<<NS, 256>>>(deg_ss, off_ss, list_ss, ss_src, ESS, ebuf, wbuf,
                               hsS, gat_b + lr * HH, oS, 1);
        }
        // relation sj (lr = l*3+1): skills -> jobs, output into oJ (init)
        {
            int lr = l * 3 + 1;
            k_gat_src<<<NS / 8, 256>>>(xs_cur, gat_Ws + (size_t)lr * HD * HH,
                                       gat_as + lr * 2 * HD, hsS, asb);
            k_alpha_d<<<cdiv(NJ, 8), 256>>>(xj_cur, vd + lr * HD * 2, adb, NJ);
            k_edge<<<cdiv(ESJ, 256), 256>>>(sj_src, sj_dst, ESJ, ESJ, asb, adb, ebuf);
            k_agg<<<NJ, 256>>>(deg_sj, off_sj, list_sj, sj_src, ESJ, ebuf, wbuf,
                               hsS, gat_b + lr * HH, oJ, 0);
        }
        // inter linears
        k_inter<<<NJ / 8, 128>>>(oJ, inter_W + (size_t)(l * 2 + 0) * HH * HD,
                                 inter_b + (l * 2 + 0) * HD, xj_nxt);
        k_inter<<<NS / 8, 128>>>(oS, inter_W + (size_t)(l * 2 + 1) * HH * HD,
                                 inter_b + (l * 2 + 1) * HD, xs_nxt);
        // swap ping-pong
        float* t;
        t = xj_cur; xj_cur = xj_nxt; xj_nxt = t;
        t = xs_cur; xs_cur = xs_nxt; xs_nxt = t;
    }

    // final projection + query + scores
    k_q<<<1, 128>>>(query, Wq, bq, out_q);
    k_final<<<NJ / 8, 128>>>(xj_cur, Wjf, bjf, out_q, out_scores, out_emb);
}

// round 4
// speedup vs baseline: 1.2004x; 1.2004x over previous
#include <cuda_runtime.h>
#include <mma.h>
#include <math.h>

using namespace nvcuda;

// ---------------- problem constants ----------------
#define NJ 30000
#define NS 12000
#define EJS 300000
#define ESJ 300000
#define ESS 150000
#define ESS_TOT (ESS + NS)   // + self loops
#define SB 384
#define HD 128
#define HH 256               // H * HID
#define NEG 0.2f

// scan chunking
#define NCH_S 12             // ceil(12000/1024)
#define NCH_J 30             // ceil(30000/1024)
#define SCAN_BLOCKS (NCH_S + NCH_J + NCH_S)   // 54

// ---------------- scratch (static device globals; no allocs) ----------------
__device__ float g_xj0[NJ * HD];
__device__ float g_xj1[NJ * HD];
__device__ float g_xs0[NS * HD];
__device__ float g_xs1[NS * HD];
__device__ float g_hsJ[NJ * HH];
__device__ float g_hsS[NS * HH];
__device__ float g_oJ[NJ * HH];
__device__ float g_oS[NS * HH];
__device__ float g_asb[NJ * 2];
__device__ float g_adb[NJ * 2];
__device__ float g_ebuf[EJS * 2];
__device__ float g_wbuf[EJS * 2];
__device__ float g_vd[6 * HD * 2];
__device__ int g_part[96];

__device__ int g_deg_js[NS], g_off_js[NS], g_cur_js[NS], g_list_js[EJS];
__device__ int g_deg_sj[NJ], g_off_sj[NJ], g_cur_sj[NJ], g_list_sj[ESJ];
__device__ int g_deg_ss[NS], g_off_ss[NS], g_cur_ss[NS], g_list_ss[ESS_TOT];

// ======================= tf32 WMMA GEMM core =======================
// Computes C[64 x ND] = x[n0:n0+64, :KD] @ W[:KD, :ND] into smem sC (ld=ND+8).
// 256 threads (8 warps), warp w -> row-tile (w>>1), col-tiles (w&1)*CT..+CT-1.
template<int KD, int ND>
__device__ __forceinline__ void gemm_tile(const float* __restrict__ x,
                                          const float* __restrict__ W,
                                          float* smem, int n0, int M) {
    constexpr int KC = 32;
    constexpr int LDA = KC + 8;        // 40
    constexpr int LDB = ND + 8;        // 136 / 264
    constexpr int CT = ND / 32;        // col-tiles per warp: 4 (N=128) or 8 (N=256)
    float* sA = smem;
    float* sB = smem + 64 * LDA;
    int tid = threadIdx.x;
    int w = tid >> 5;
    int rt = w >> 1;
    int c0 = (w & 1) * CT;

    wmma::fragment<wmma::accumulator, 16, 16, 8, float> acc[CT];
    #pragma unroll
    for (int j = 0; j < CT; j++) wmma::fill_fragment(acc[j], 0.0f);

    for (int k0 = 0; k0 < KD; k0 += KC) {
        __syncthreads();
        // load A chunk 64x32
        #pragma unroll
        for (int ld = 0; ld < 2; ld++) {
            int id = tid + ld * 256;        // 0..511 float4 slots
            int r = id >> 3;
            int c4 = (id & 7) * 4;
            float4 v = make_float4(0.f, 0.f, 0.f, 0.f);
            int row = n0 + r;
            if (row < M) v = *(const float4*)&x[(size_t)row * KD + k0 + c4];
            *(float4*)&sA[r * LDA + c4] = v;
        }
        // load B chunk 32xND
        #pragma unroll
        for (int ld = 0; ld < ND / 32; ld++) {
            int id = tid + ld * 256;        // float4 slots
            int r = (id * 4) / ND;
            int c = (id * 4) % ND;
            *(float4*)&sB[r * LDB + c] = *(const float4*)&W[(size_t)(k0 + r) * ND + c];
        }
        __syncthreads();
        #pragma unroll
        for (int kk = 0; kk < KC / 8; kk++) {
            wmma::fragment<wmma::matrix_a, 16, 16, 8, wmma::precision::tf32, wmma::row_major> af;
            wmma::load_matrix_sync(af, &sA[rt * 16 * LDA + kk * 8], LDA);
            #pragma unroll
            for (int t = 0; t < af.num_elements; t++) af.x[t] = wmma::__float_to_tf32(af.x[t]);
            #pragma unroll
            for (int j = 0; j < CT; j++) {
                wmma::fragment<wmma::matrix_b, 16, 16, 8, wmma::precision::tf32, wmma::row_major> bf;
                wmma::load_matrix_sync(bf, &sB[kk * 8 * LDB + (c0 + j) * 16], LDB);
                #pragma unroll
                for (int t = 0; t < bf.num_elements; t++) bf.x[t] = wmma::__float_to_tf32(bf.x[t]);
                wmma::mma_sync(acc[j], af, bf, acc[j]);
            }
        }
    }
    __syncthreads();
    float* sC = smem;
    #pragma unroll
    for (int j = 0; j < CT; j++)
        wmma::store_matrix_sync(&sC[rt * 16 * LDB + (c0 + j) * 16], acc[j], LDB, wmma::mem_row_major);
    __syncthreads();
}

// lin0: y = relu(LN(x@W + b)*g + be); K=384, N=128
__global__ __launch_bounds__(256) void k_lin0_t(
    const float* __restrict__ x, const float* __restrict__ W,
    const float* __restrict__ b, const float* __restrict__ g,
    const float* __restrict__ be, float* __restrict__ y, int M) {
    extern __shared__ float smem[];
    int n0 = blockIdx.x * 64;
    gemm_tile<SB, HD>(x, W, smem, n0, M);
    constexpr int LDC = HD + 8;
    float* sC = smem;
    int tid = threadIdx.x, w = tid >> 5, lane = tid & 31;
    float4 b4 = *(const float4*)&b[lane * 4];
    float4 g4 = *(const float4*)&g[lane * 4];
    float4 be4 = *(const float4*)&be[lane * 4];
    #pragma unroll
    for (int r8 = 0; r8 < 8; r8++) {
        int r = w * 8 + r8;
        int row = n0 + r;
        float4 v = *(float4*)&sC[r * LDC + lane * 4];
        v.x += b4.x; v.y += b4.y; v.z += b4.z; v.w += b4.w;
        float s = v.x + v.y + v.z + v.w;
        float s2 = v.x * v.x + v.y * v.y + v.z * v.z + v.w * v.w;
        #pragma unroll
        for (int o = 16; o; o >>= 1) {
            s += __shfl_xor_sync(0xFFFFFFFFu, s, o);
            s2 += __shfl_xor_sync(0xFFFFFFFFu, s2, o);
        }
        float mu = s * (1.0f / HD);
        float var = s2 * (1.0f / HD) - mu * mu;
        float rs = rsqrtf(var + 1e-5f);
        float4 ov;
        ov.x = fmaxf((v.x - mu) * rs * g4.x + be4.x, 0.0f);
        ov.y = fmaxf((v.y - mu) * rs * g4.y + be4.y, 0.0f);
        ov.z = fmaxf((v.z - mu) * rs * g4.z + be4.z, 0.0f);
        ov.w = fmaxf((v.w - mu) * rs * g4.w + be4.w, 0.0f);
        if (row < M) *(float4*)&y[(size_t)row * HD + lane * 4] = ov;
    }
}

// gat_src: hs = x@Ws (no bias); alpha[n,h] = sum_c hs[n,h,c]*a[h,c]; K=128, N=256
__global__ __launch_bounds__(256) void k_gat_src_t(
    const float* __restrict__ x, const float* __restrict__ W,
    const float* __restrict__ avec, float* __restrict__ hs,
    float* __restrict__ alpha, int M) {
    extern __shared__ float smem[];
    int n0 = blockIdx.x * 64;
    gemm_tile<HD, HH>(x, W, smem, n0, M);
    constexpr int LDC = HH + 8;
    float* sC = smem;
    int tid = threadIdx.x, w = tid >> 5, lane = tid & 31;
    // store hs
    #pragma unroll
    for (int ld = 0; ld < 16; ld++) {
        int id = tid + ld * 256;           // 0..4095 float4 slots
        int r = id >> 6;
        int c = (id & 63) * 4;
        int row = n0 + r;
        if (row < M) *(float4*)&hs[(size_t)row * HH + c] = *(float4*)&sC[r * LDC + c];
    }
    // alpha reductions
    float4 av0 = *(const float4*)&avec[lane * 4];
    float4 av1 = *(const float4*)&avec[HD + lane * 4];
    #pragma unroll
    for (int r8 = 0; r8 < 8; r8++) {
        int r = w * 8 + r8;
        int row = n0 + r;
        float4 v0 = *(float4*)&sC[r * LDC + lane * 4];
        float4 v1 = *(float4*)&sC[r * LDC + HD + lane * 4];
        float a0 = v0.x * av0.x + v0.y * av0.y + v0.z * av0.z + v0.w * av0.w;
        float a1 = v1.x * av1.x + v1.y * av1.y + v1.z * av1.z + v1.w * av1.w;
        #pragma unroll
        for (int o = 16; o; o >>= 1) {
            a0 += __shfl_xor_sync(0xFFFFFFFFu, a0, o);
            a1 += __shfl_xor_sync(0xFFFFFFFFu, a1, o);
        }
        if (lane == 0 && row < M) {
            alpha[row * 2 + 0] = a0;
            alpha[row * 2 + 1] = a1;
        }
    }
}

// inter: y = relu(x@W + b); K=256, N=128
__global__ __launch_bounds__(256) void k_inter_t(
    const float* __restrict__ x, const float* __restrict__ W,
    const float* __restrict__ b, float* __restrict__ y, int M) {
    extern __shared__ float smem[];
    int n0 = blockIdx.x * 64;
    gemm_tile<HH, HD>(x, W, smem, n0, M);
    constexpr int LDC = HD + 8;
    float* sC = smem;
    int tid = threadIdx.x;
    #pragma unroll
    for (int ld = 0; ld < 8; ld++) {
        int id = tid + ld * 256;           // 0..2047 float4 slots
        int r = id >> 5;
        int c = (id & 31) * 4;
        int row = n0 + r;
        if (row < M) {
            float4 v = *(float4*)&sC[r * LDC + c];
            float4 bb = *(const float4*)&b[c];
            float4 ov;
            ov.x = fmaxf(v.x + bb.x, 0.0f);
            ov.y = fmaxf(v.y + bb.y, 0.0f);
            ov.z = fmaxf(v.z + bb.z, 0.0f);
            ov.w = fmaxf(v.w + bb.w, 0.0f);
            *(float4*)&y[(size_t)row * HD + c] = ov;
        }
    }
}

// final: emb = xj@Wjf + bjf; scores = emb@q; K=128, N=128
__global__ __launch_bounds__(256) void k_final_t(
    const float* __restrict__ x, const float* __restrict__ W,
    const float* __restrict__ b, const float* __restrict__ q,
    float* __restrict__ scores, float* __restrict__ emb, int M) {
    extern __shared__ float smem[];
    int n0 = blockIdx.x * 64;
    gemm_tile<HD, HD>(x, W, smem, n0, M);
    constexpr int LDC = HD + 8;
    float* sC = smem;
    int tid = threadIdx.x, w = tid >> 5, lane = tid & 31;
    float4 b4 = *(const float4*)&b[lane * 4];
    float4 q4 = *(const float4*)&q[lane * 4];
    #pragma unroll
    for (int r8 = 0; r8 < 8; r8++) {
        int r = w * 8 + r8;
        int row = n0 + r;
        float4 v = *(float4*)&sC[r * LDC + lane * 4];
        v.x += b4.x; v.y += b4.y; v.z += b4.z; v.w += b4.w;
        float p = v.x * q4.x + v.y * q4.y + v.z * q4.z + v.w * q4.w;
        #pragma unroll
        for (int o = 16; o; o >>= 1) p += __shfl_xor_sync(0xFFFFFFFFu, p, o);
        if (row < M) {
            *(float4*)&emb[(size_t)row * HD + lane * 4] = v;
            if (lane == 0) scores[row] = p;
        }
    }
}

// ======================= small fp32 kernels =======================

// alpha_d[n,h] = x[n,:] @ vd[:,h]
__global__ void k_alpha_d(const float* __restrict__ x, const float* __restrict__ vd,
                          float* __restrict__ ad, int N) {
    int wp = threadIdx.x >> 5, lane = threadIdx.x & 31;
    int row = blockIdx.x * 8 + wp;
    if (row >= N) return;
    float a0 = 0.0f, a1 = 0.0f;
    for (int k = lane; k < HD; k += 32) {
        float xv = x[row * HD + k];
        a0 += xv * vd[k * 2 + 0];
        a1 += xv * vd[k * 2 + 1];
    }
    #pragma unroll
    for (int o = 16; o; o >>= 1) {
        a0 += __shfl_xor_sync(0xFFFFFFFFu, a0, o);
        a1 += __shfl_xor_sync(0xFFFFFFFFu, a1, o);
    }
    if (lane == 0) { ad[row * 2 + 0] = a0; ad[row * 2 + 1] = a1; }
}

// vd[lr][k][h] = sum_c Wd[lr][k][h*128+c] * a_d[lr][h][c]
__global__ void k_prep(const float* __restrict__ Wd, const float* __restrict__ adv,
                       float* __restrict__ vd) {
    int lr = blockIdx.x;
    int k = threadIdx.x >> 1, h = threadIdx.x & 1;
    const float* wrow = Wd + ((size_t)lr * HD + k) * HH + h * HD;
    const float* arow = adv + (lr * 2 + h) * HD;
    float s = 0.0f;
    for (int c = 0; c < HD; c++) s += wrow[c] * arow[c];
    vd[lr * (HD * 2) + k * 2 + h] = s;
}

__global__ void k_count(const int* __restrict__ dst, int E, int nReal,
                        int* __restrict__ deg) {
    int e = blockIdx.x * blockDim.x + threadIdx.x;
    if (e >= E) return;
    int d = (e < nReal) ? dst[e] : (e - nReal);
    atomicAdd(&deg[d], 1);
}

// ---------- 3-phase multi-block scan over the three deg arrays ----------
__device__ __forceinline__ void scan_map(int b, int& arr, int& chunk) {
    if (b < NCH_S) { arr = 0; chunk = b; }
    else if (b < NCH_S + NCH_J) { arr = 1; chunk = b - NCH_S; }
    else { arr = 2; chunk = b - NCH_S - NCH_J; }
}

__global__ void k_scanA(const int* __restrict__ d0, int* __restrict__ o0,
                        const int* __restrict__ d1, int* __restrict__ o1,
                        const int* __restrict__ d2, int* __restrict__ o2,
                        int* __restrict__ part) {
    int arr, chunk;
    scan_map(blockIdx.x, arr, chunk);
    const int* deg = (arr == 0) ? d0 : (arr == 1) ? d1 : d2;
    int* off = (arr == 0) ? o0 : (arr == 1) ? o1 : o2;
    int n = (arr == 1) ? NJ : NS;
    int i = chunk * 1024 + threadIdx.x;
    int v = (i < n) ? deg[i] : 0;
    int lane = threadIdx.x & 31, wid = threadIdx.x >> 5;
    int incl = v;
    #pragma unroll
    for (int o = 1; o < 32; o <<= 1) {
        int t = __shfl_up_sync(0xFFFFFFFFu, incl, o);
        if (lane >= o) incl += t;
    }
    __shared__ int ws[32];
    if (lane == 31) ws[wid] = incl;
    __syncthreads();
    if (wid == 0) {
        int t2 = ws[lane];
        int inc2 = t2;
        #pragma unroll
        for (int o = 1; o < 32; o <<= 1) {
            int u = __shfl_up_sync(0xFFFFFFFFu, inc2, o);
            if (lane >= o) inc2 += u;
        }
        ws[lane] = inc2;
    }
    __syncthreads();
    int base = (wid > 0) ? ws[wid - 1] : 0;
    if (i < n) off[i] = base + incl - v;
    if (threadIdx.x == 1023) part[arr * 32 + chunk] = base + incl;
}

__global__ void k_scanB(int* __restrict__ part) {
    int w = threadIdx.x >> 5, lane = threadIdx.x & 31;
    if (w >= 3) return;
    int nc = (w == 1) ? NCH_J : NCH_S;
    int v = (lane < nc) ? part[w * 32 + lane] : 0;
    int incl = v;
    #pragma unroll
    for (int o = 1; o < 32; o <<= 1) {
        int t = __shfl_up_sync(0xFFFFFFFFu, incl, o);
        if (lane >= o) incl += t;
    }
    if (lane < nc) part[w * 32 + lane] = incl - v;   // exclusive
}

__global__ void k_scanC(int* __restrict__ o0, int* __restrict__ c0,
                        int* __restrict__ o1, int* __restrict__ c1,
                        int* __restrict__ o2, int* __restrict__ c2,
                        const int* __restrict__ part) {
    int arr, chunk;
    scan_map(blockIdx.x, arr, chunk);
    int* off = (arr == 0) ? o0 : (arr == 1) ? o1 : o2;
    int* cur = (arr == 0) ? c0 : (arr == 1) ? c1 : c2;
    int n = (arr == 1) ? NJ : NS;
    int i = chunk * 1024 + threadIdx.x;
    if (i < n) {
        int v = off[i] + part[arr * 32 + chunk];
        off[i] = v;
        cur[i] = v;
    }
}

__global__ void k_scatter(const int* __restrict__ dst, int E, int nReal,
                          int* __restrict__ cur, int* __restrict__ list) {
    int e = blockIdx.x * blockDim.x + threadIdx.x;
    if (e >= E) return;
    int d = (e < nReal) ? dst[e] : (e - nReal);
    int pos = atomicAdd(&cur[d], 1);
    list[pos] = e;
}

// e[edge,h] = leaky_relu(alpha_s[src,h] + alpha_d[dst,h])
__global__ void k_edge(const int* __restrict__ src, const int* __restrict__ dst,
                       int E, int nReal, const float* __restrict__ as,
                       const float* __restrict__ ad, float* __restrict__ ebuf) {
    int e = blockIdx.x * blockDim.x + threadIdx.x;
    if (e >= E) return;
    int s, d;
    if (e < nReal) { s = src[e]; d = dst[e]; } else { s = d = e - nReal; }
    #pragma unroll
    for (int h = 0; h < 2; h++) {
        float v = as[s * 2 + h] + ad[d * 2 + h];
        ebuf[e * 2 + h] = (v > 0.0f) ? v : NEG * v;
    }
}

// per-dst softmax + weighted message sum. 256 threads per dst node.
__global__ void k_agg(const int* __restrict__ deg, const int* __restrict__ off,
                      const int* __restrict__ list, const int* __restrict__ srcArr,
                      int nReal, const float* __restrict__ ebuf, float* __restrict__ wbuf,
                      const float* __restrict__ hs, const float* __restrict__ bias,
                      float* __restrict__ out, int accum) {
    __shared__ float smax[2][4], sden[2][4], sinv[2];
    int d = blockIdx.x;
    int dg = deg[d];
    int st = off[d];
    int tid = threadIdx.x, lane = tid & 31, w = tid >> 5;
    int h = w & 1, qq = w >> 1;
    // pass 1: max over segment (8 warps: 4 quarters x 2 heads)
    float m = -INFINITY;
    for (int i = qq * 32 + lane; i < dg; i += 128) {
        int e = list[st + i];
        m = fmaxf(m, ebuf[e * 2 + h]);
    }
    #pragma unroll
    for (int o = 16; o; o >>= 1) m = fmaxf(m, __shfl_xor_sync(0xFFFFFFFFu, m, o));
    if (lane == 0) smax[h][qq] = m;
    __syncthreads();
    float mm = fmaxf(fmaxf(smax[h][0], smax[h][1]), fmaxf(smax[h][2], smax[h][3]));
    // pass 2: exp + denominator
    float den = 0.0f;
    for (int i = qq * 32 + lane; i < dg; i += 128) {
        int e = list[st + i];
        float t = __expf(ebuf[e * 2 + h] - mm);
        wbuf[e * 2 + h] = t;
        den += t;
    }
    #pragma unroll
    for (int o = 16; o; o >>= 1) den += __shfl_xor_sync(0xFFFFFFFFu, den, o);
    if (lane == 0) sden[h][qq] = den;
    __syncthreads();
    if (tid < 2)
        sinv[tid] = 1.0f / (sden[tid][0] + sden[tid][1] + sden[tid][2] + sden[tid][3] + 1e-16f);
    __syncthreads();
    // pass 3: weighted gather, 4-wide unrolled for MLP
    int h2 = tid >> 7;
    float acc = 0.0f;
    int i = 0;
    for (; i + 4 <= dg; i += 4) {
        int e0 = list[st + i], e1 = list[st + i + 1], e2 = list[st + i + 2], e3 = list[st + i + 3];
        int s0 = (e0 < nReal) ? srcArr[e0] : e0 - nReal;
        int s1 = (e1 < nReal) ? srcArr[e1] : e1 - nReal;
        int s2 = (e2 < nReal) ? srcArr[e2] : e2 - nReal;
        int s3 = (e3 < nReal) ? srcArr[e3] : e3 - nReal;
        float w0 = wbuf[e0 * 2 + h2], w1 = wbuf[e1 * 2 + h2];
        float w2 = wbuf[e2 * 2 + h2], w3 = wbuf[e3 * 2 + h2];
        float v0 = hs[(size_t)s0 * HH + tid];
        float v1 = hs[(size_t)s1 * HH + tid];
        float v2 = hs[(size_t)s2 * HH + tid];
        float v3 = hs[(size_t)s3 * HH + tid];
        acc += w0 * v0 + w1 * v1 + w2 * v2 + w3 * v3;
    }
    for (; i < dg; i++) {
        int e = list[st + i];
        int s = (e < nReal) ? srcArr[e] : e - nReal;
        acc += wbuf[e * 2 + h2] * hs[(size_t)s * HH + tid];
    }
    float o = acc * sinv[h2] + bias[tid];
    size_t oi = (size_t)d * HH + tid;
    if (accum) out[oi] += o; else out[oi] = o;
}

// q = query @ Wq + bq
__global__ void k_q(const float* __restrict__ query, const float* __restrict__ Wq,
                    const float* __restrict__ bq, float* __restrict__ q) {
    int c = threadIdx.x;
    float acc = bq[c];
    for (int k = 0; k < SB; k++) acc += query[k] * Wq[k * HD + c];
    q[c] = acc;
}

// ---------------- host launch ----------------
static inline int cdiv(int a, int b) { return (a + b - 1) / b; }

extern "C" void kernel_launch(void* const* d_in, const int* in_sizes, int n_in,
                              void* d_out, int out_size) {
    const float* x_job   = (const float*)d_in[0];
    const float* x_skill = (const float*)d_in[1];
    const int* js_src = (const int*)d_in[2];
    const int* js_dst = (const int*)d_in[3];
    const int* sj_src = (const int*)d_in[4];
    const int* sj_dst = (const int*)d_in[5];
    const int* ss_src = (const int*)d_in[6];
    const int* ss_dst = (const int*)d_in[7];
    const float* query    = (const float*)d_in[8];
    const float* W0_job   = (const float*)d_in[9];
    const float* b0_job   = (const float*)d_in[10];
    const float* g0_job   = (const float*)d_in[11];
    const float* be0_job  = (const float*)d_in[12];
    const float* W0_skill = (const float*)d_in[13];
    const float* b0_skill = (const float*)d_in[14];
    const float* g0_skill = (const float*)d_in[15];
    const float* be0_skill= (const float*)d_in[16];
    const float* gat_Ws = (const float*)d_in[17];
    const float* gat_Wd = (const float*)d_in[18];
    const float* gat_as = (const float*)d_in[19];
    const float* gat_ad = (const float*)d_in[20];
    const float* gat_b  = (const float*)d_in[21];
    const float* inter_W= (const float*)d_in[22];
    const float* inter_b= (const float*)d_in[23];
    const float* Wjf = (const float*)d_in[24];
    const float* bjf = (const float*)d_in[25];
    const float* Wq  = (const float*)d_in[26];
    const float* bq  = (const float*)d_in[27];

    float* out = (float*)d_out;
    float* out_scores = out;
    float* out_emb = out + NJ;
    float* out_q = out + NJ + (size_t)NJ * HD;

    float *xj0, *xj1, *xs0, *xs1, *hsJ, *hsS, *oJ, *oS, *asb, *adb, *ebuf, *wbuf, *vd;
    int *part;
    int *deg_js, *off_js, *cur_js, *list_js;
    int *deg_sj, *off_sj, *cur_sj, *list_sj;
    int *deg_ss, *off_ss, *cur_ss, *list_ss;
    cudaGetSymbolAddress((void**)&xj0, g_xj0);
    cudaGetSymbolAddress((void**)&xj1, g_xj1);
    cudaGetSymbolAddress((void**)&xs0, g_xs0);
    cudaGetSymbolAddress((void**)&xs1, g_xs1);
    cudaGetSymbolAddress((void**)&hsJ, g_hsJ);
    cudaGetSymbolAddress((void**)&hsS, g_hsS);
    cudaGetSymbolAddress((void**)&oJ, g_oJ);
    cudaGetSymbolAddress((void**)&oS, g_oS);
    cudaGetSymbolAddress((void**)&asb, g_asb);
    cudaGetSymbolAddress((void**)&adb, g_adb);
    cudaGetSymbolAddress((void**)&ebuf, g_ebuf);
    cudaGetSymbolAddress((void**)&wbuf, g_wbuf);
    cudaGetSymbolAddress((void**)&vd, g_vd);
    cudaGetSymbolAddress((void**)&part, g_part);
    cudaGetSymbolAddress((void**)&deg_js, g_deg_js);
    cudaGetSymbolAddress((void**)&off_js, g_off_js);
    cudaGetSymbolAddress((void**)&cur_js, g_cur_js);
    cudaGetSymbolAddress((void**)&list_js, g_list_js);
    cudaGetSymbolAddress((void**)&deg_sj, g_deg_sj);
    cudaGetSymbolAddress((void**)&off_sj, g_off_sj);
    cudaGetSymbolAddress((void**)&cur_sj, g_cur_sj);
    cudaGetSymbolAddress((void**)&list_sj, g_list_sj);
    cudaGetSymbolAddress((void**)&deg_ss, g_deg_ss);
    cudaGetSymbolAddress((void**)&off_ss, g_off_ss);
    cudaGetSymbolAddress((void**)&cur_ss, g_cur_ss);
    cudaGetSymbolAddress((void**)&list_ss, g_list_ss);

    // dynamic smem sizes for the wmma kernels
    const int SM_N128 = (64 * (HD + 8)) * 4;        // 34816 B (sC dominates)
    const int SM_N256 = (64 * (HH + 8)) * 4;        // 67584 B
    cudaFuncSetAttribute(k_lin0_t,    cudaFuncAttributeMaxDynamicSharedMemorySize, SM_N128);
    cudaFuncSetAttribute(k_inter_t,   cudaFuncAttributeMaxDynamicSharedMemorySize, SM_N128);
    cudaFuncSetAttribute(k_final_t,   cudaFuncAttributeMaxDynamicSharedMemorySize, SM_N128);
    cudaFuncSetAttribute(k_gat_src_t, cudaFuncAttributeMaxDynamicSharedMemorySize, SM_N256);

    const int GJ = cdiv(NJ, 64);   // 469
    const int GS = cdiv(NS, 64);   // 188

    // --- CSR build ---
    cudaMemsetAsync(deg_js, 0, NS * sizeof(int));
    cudaMemsetAsync(deg_sj, 0, NJ * sizeof(int));
    cudaMemsetAsync(deg_ss, 0, NS * sizeof(int));
    k_count<<<cdiv(EJS, 256), 256>>>(js_dst, EJS, EJS, deg_js);
    k_count<<<cdiv(ESJ, 256), 256>>>(sj_dst, ESJ, ESJ, deg_sj);
    k_count<<<cdiv(ESS_TOT, 256), 256>>>(ss_dst, ESS_TOT, ESS, deg_ss);
    k_scanA<<<SCAN_BLOCKS, 1024>>>(deg_js, off_js, deg_sj, off_sj, deg_ss, off_ss, part);
    k_scanB<<<1, 128>>>(part);
    k_scanC<<<SCAN_BLOCKS, 1024>>>(off_js, cur_js, off_sj, cur_sj, off_ss, cur_ss, part);
    k_scatter<<<cdiv(EJS, 256), 256>>>(js_dst, EJS, EJS, cur_js, list_js);
    k_scatter<<<cdiv(ESJ, 256), 256>>>(sj_dst, ESJ, ESJ, cur_sj, list_sj);
    k_scatter<<<cdiv(ESS_TOT, 256), 256>>>(ss_dst, ESS_TOT, ESS, cur_ss, list_ss);

    // --- init linears + LN + relu ---
    k_lin0_t<<<GJ, 256, SM_N128>>>(x_job, W0_job, b0_job, g0_job, be0_job, xj0, NJ);
    k_lin0_t<<<GS, 256, SM_N128>>>(x_skill, W0_skill, b0_skill, g0_skill, be0_skill, xs0, NS);
    k_prep<<<6, 256>>>(gat_Wd, gat_ad, vd);

    float* xj_cur = xj0; float* xs_cur = xs0;
    float* xj_nxt = xj1; float* xs_nxt = xs1;

    for (int l = 0; l < 2; l++) {
        // relation js (lr = l*3+0): jobs -> skills, into oS (init)
        {
            int lr = l * 3 + 0;
            k_gat_src_t<<<GJ, 256, SM_N256>>>(xj_cur, gat_Ws + (size_t)lr * HD * HH,
                                              gat_as + lr * 2 * HD, hsJ, asb, NJ);
            k_alpha_d<<<cdiv(NS, 8), 256>>>(xs_cur, vd + lr * HD * 2, adb, NS);
            k_edge<<<cdiv(EJS, 256), 256>>>(js_src, js_dst, EJS, EJS, asb, adb, ebuf);
            k_agg<<<NS, 256>>>(deg_js, off_js, list_js, js_src, EJS, ebuf, wbuf,
                               hsJ, gat_b + lr * HH, oS, 0);
        }
        // relation ss (lr = l*3+2): skills -> skills (+self loops), accumulate into oS
        {
            int lr = l * 3 + 2;
            k_gat_src_t<<<GS, 256, SM_N256>>>(xs_cur, gat_Ws + (size_t)lr * HD * HH,
                                              gat_as + lr * 2 * HD, hsS, asb, NS);
            k_alpha_d<<<cdiv(NS, 8), 256>>>(xs_cur, vd + lr * HD * 2, adb, NS);
            k_edge<<<cdiv(ESS_TOT, 256), 256>>>(ss_src, ss_dst, ESS_TOT, ESS, asb, adb, ebuf);
            k_agg<<<NS, 256>>>(deg_ss, off_ss, list_ss, ss_src, ESS, ebuf, wbuf,
                               hsS, gat_b + lr * HH, oS, 1);
        }
        // relation sj (lr = l*3+1): skills -> jobs, into oJ (init)
        {
            int lr = l * 3 + 1;
            k_gat_src_t<<<GS, 256, SM_N256>>>(xs_cur, gat_Ws + (size_t)lr * HD * HH,
                                              gat_as + lr * 2 * HD, hsS, asb, NS);
            k_alpha_d<<<cdiv(NJ, 8), 256>>>(xj_cur, vd + lr * HD * 2, adb, NJ);
            k_edge<<<cdiv(ESJ, 256), 256>>>(sj_src, sj_dst, ESJ, ESJ, asb, adb, ebuf);
            k_agg<<<NJ, 256>>>(deg_sj, off_sj, list_sj, sj_src, ESJ, ebuf, wbuf,
                               hsS, gat_b + lr * HH, oJ, 0);
        }
        // inter linears
        k_inter_t<<<GJ, 256, SM_N128>>>(oJ, inter_W + (size_t)(l * 2 + 0) * HH * HD,
                                        inter_b + (l * 2 + 0) * HD, xj_nxt, NJ);
        k_inter_t<<<GS, 256, SM_N128>>>(oS, inter_W + (size_t)(l * 2 + 1) * HH * HD,
                                        inter_b + (l * 2 + 1) * HD, xs_nxt, NS);
        float* t;
        t = xj_cur; xj_cur = xj_nxt; xj_nxt = t;
        t = xs_cur; xs_cur = xs_nxt; xs_nxt = t;
    }

    // final projection + query + scores
    k_q<<<1, 128>>>(query, Wq, bq, out_q);
    k_final_t<<<GJ, 256, SM_N128>>>(xj_cur, Wjf, bjf, out_q, out_scores, out_emb, NJ);
}

// round 12
// speedup vs baseline: 1.5592x; 1.2989x over previous
#include <cuda_runtime.h>
#include <mma.h>
#include <math.h>

using namespace nvcuda;

// ---------------- problem constants ----------------
#define NJ 30000
#define NS 12000
#define EJS 300000
#define ESJ 300000
#define ESS 150000
#define ESS_TOT (ESS + NS)   // + self loops
#define TOTE (EJS + ESJ + ESS_TOT)   // 762000
#define NDTOT (NS + NJ + NS)         // 54000 combined dst nodes
#define NCHUNK 53                    // ceil(54000/1024)
#define SB 384
#define HD 128
#define HH 256               // H * HID
#define NEG 0.2f
#define AGG_CAP 1024

// ---------------- scratch (static device globals; no allocs) ----------------
__device__ float g_xj0[NJ * HD];
__device__ float g_xj1[NJ * HD];
__device__ float g_xs0[NS * HD];
__device__ float g_xs1[NS * HD];
__device__ float g_hsJ[NJ * HH];
__device__ float g_hsS1[NS * HH];
__device__ float g_hsS2[NS * HH];
__device__ float g_oJ[NJ * HH];
__device__ float g_oS[NS * HH];
__device__ float g_asbJ[NJ * 2];
__device__ float g_asbS1[NS * 2];
__device__ float g_asbS2[NS * 2];
__device__ float g_adb0[NS * 2];
__device__ float g_adb1[NS * 2];
__device__ float g_adb2[NJ * 2];
__device__ float g_vd[6 * HD * 2];
__device__ int g_part[64];
__device__ int g_deg[NDTOT], g_off[NDTOT], g_cur[NDTOT];
__device__ int g_list[TOTE];

// ======================= tf32 WMMA GEMM core =======================
template<int KD, int ND>
__device__ __forceinline__ void gemm_tile(const float* __restrict__ x,
                                          const float* __restrict__ W,
                                          float* smem, int n0, int M) {
    constexpr int KC = 32;
    constexpr int LDA = KC + 8;
    constexpr int LDB = ND + 8;
    constexpr int CT = ND / 32;
    float* sA = smem;
    float* sB = smem + 64 * LDA;
    int tid = threadIdx.x;
    int w = tid >> 5;
    int rt = w >> 1;
    int c0 = (w & 1) * CT;

    wmma::fragment<wmma::accumulator, 16, 16, 8, float> acc[CT];
    #pragma unroll
    for (int j = 0; j < CT; j++) wmma::fill_fragment(acc[j], 0.0f);

    for (int k0 = 0; k0 < KD; k0 += KC) {
        __syncthreads();
        #pragma unroll
        for (int ld = 0; ld < 2; ld++) {
            int id = tid + ld * 256;
            int r = id >> 3;
            int c4 = (id & 7) * 4;
            float4 v = make_float4(0.f, 0.f, 0.f, 0.f);
            int row = n0 + r;
            if (row < M) v = *(const float4*)&x[(size_t)row * KD + k0 + c4];
            *(float4*)&sA[r * LDA + c4] = v;
        }
        #pragma unroll
        for (int ld = 0; ld < ND / 32; ld++) {
            int id = tid + ld * 256;
            int r = (id * 4) / ND;
            int c = (id * 4) % ND;
            *(float4*)&sB[r * LDB + c] = *(const float4*)&W[(size_t)(k0 + r) * ND + c];
        }
        __syncthreads();
        #pragma unroll
        for (int kk = 0; kk < KC / 8; kk++) {
            wmma::fragment<wmma::matrix_a, 16, 16, 8, wmma::precision::tf32, wmma::row_major> af;
            wmma::load_matrix_sync(af, &sA[rt * 16 * LDA + kk * 8], LDA);
            #pragma unroll
            for (int t = 0; t < af.num_elements; t++) af.x[t] = wmma::__float_to_tf32(af.x[t]);
            #pragma unroll
            for (int j = 0; j < CT; j++) {
                wmma::fragment<wmma::matrix_b, 16, 16, 8, wmma::precision::tf32, wmma::row_major> bf;
                wmma::load_matrix_sync(bf, &sB[kk * 8 * LDB + (c0 + j) * 16], LDB);
                #pragma unroll
                for (int t = 0; t < bf.num_elements; t++) bf.x[t] = wmma::__float_to_tf32(bf.x[t]);
                wmma::mma_sync(acc[j], af, bf, acc[j]);
            }
        }
    }
    __syncthreads();
    float* sC = smem;
    #pragma unroll
    for (int j = 0; j < CT; j++)
        wmma::store_matrix_sync(&sC[rt * 16 * LDB + (c0 + j) * 16], acc[j], LDB, wmma::mem_row_major);
    __syncthreads();
}

// lin0: y = relu(LN(x@W + b)*g + be); K=384, N=128
__global__ __launch_bounds__(256) void k_lin0_t(
    const float* __restrict__ x, const float* __restrict__ W,
    const float* __restrict__ b, const float* __restrict__ g,
    const float* __restrict__ be, float* __restrict__ y, int M) {
    extern __shared__ float smem[];
    int n0 = blockIdx.x * 64;
    gemm_tile<SB, HD>(x, W, smem, n0, M);
    constexpr int LDC = HD + 8;
    float* sC = smem;
    int tid = threadIdx.x, w = tid >> 5, lane = tid & 31;
    float4 b4 = *(const float4*)&b[lane * 4];
    float4 g4 = *(const float4*)&g[lane * 4];
    float4 be4 = *(const float4*)&be[lane * 4];
    #pragma unroll
    for (int r8 = 0; r8 < 8; r8++) {
        int r = w * 8 + r8;
        int row = n0 + r;
        float4 v = *(float4*)&sC[r * LDC + lane * 4];
        v.x += b4.x; v.y += b4.y; v.z += b4.z; v.w += b4.w;
        float s = v.x + v.y + v.z + v.w;
        float s2 = v.x * v.x + v.y * v.y + v.z * v.z + v.w * v.w;
        #pragma unroll
        for (int o = 16; o; o >>= 1) {
            s += __shfl_xor_sync(0xFFFFFFFFu, s, o);
            s2 += __shfl_xor_sync(0xFFFFFFFFu, s2, o);
        }
        float mu = s * (1.0f / HD);
        float var = s2 * (1.0f / HD) - mu * mu;
        float rs = rsqrtf(var + 1e-5f);
        float4 ov;
        ov.x = fmaxf((v.x - mu) * rs * g4.x + be4.x, 0.0f);
        ov.y = fmaxf((v.y - mu) * rs * g4.y + be4.y, 0.0f);
        ov.z = fmaxf((v.z - mu) * rs * g4.z + be4.z, 0.0f);
        ov.w = fmaxf((v.w - mu) * rs * g4.w + be4.w, 0.0f);
        if (row < M) *(float4*)&y[(size_t)row * HD + lane * 4] = ov;
    }
}

// gat_src: hs = x@Ws; alpha[n,h] = sum_c hs[n,h,c]*a[h,c]; K=128, N=256
__global__ __launch_bounds__(256) void k_gat_src_t(
    const float* __restrict__ x, const float* __restrict__ W,
    const float* __restrict__ avec, float* __restrict__ hs,
    float* __restrict__ alpha, int M) {
    extern __shared__ float smem[];
    int n0 = blockIdx.x * 64;
    gemm_tile<HD, HH>(x, W, smem, n0, M);
    constexpr int LDC = HH + 8;
    float* sC = smem;
    int tid = threadIdx.x, w = tid >> 5, lane = tid & 31;
    #pragma unroll
    for (int ld = 0; ld < 16; ld++) {
        int id = tid + ld * 256;
        int r = id >> 6;
        int c = (id & 63) * 4;
        int row = n0 + r;
        if (row < M) *(float4*)&hs[(size_t)row * HH + c] = *(float4*)&sC[r * LDC + c];
    }
    float4 av0 = *(const float4*)&avec[lane * 4];
    float4 av1 = *(const float4*)&avec[HD + lane * 4];
    #pragma unroll
    for (int r8 = 0; r8 < 8; r8++) {
        int r = w * 8 + r8;
        int row = n0 + r;
        float4 v0 = *(float4*)&sC[r * LDC + lane * 4];
        float4 v1 = *(float4*)&sC[r * LDC + HD + lane * 4];
        float a0 = v0.x * av0.x + v0.y * av0.y + v0.z * av0.z + v0.w * av0.w;
        float a1 = v1.x * av1.x + v1.y * av1.y + v1.z * av1.z + v1.w * av1.w;
        #pragma unroll
        for (int o = 16; o; o >>= 1) {
            a0 += __shfl_xor_sync(0xFFFFFFFFu, a0, o);
            a1 += __shfl_xor_sync(0xFFFFFFFFu, a1, o);
        }
        if (lane == 0 && row < M) {
            alpha[row * 2 + 0] = a0;
            alpha[row * 2 + 1] = a1;
        }
    }
}

// inter: y = relu(x@W + b); K=256, N=128
__global__ __launch_bounds__(256) void k_inter_t(
    const float* __restrict__ x, const float* __restrict__ W,
    const float* __restrict__ b, float* __restrict__ y, int M) {
    extern __shared__ float smem[];
    int n0 = blockIdx.x * 64;
    gemm_tile<HH, HD>(x, W, smem, n0, M);
    constexpr int LDC = HD + 8;
    float* sC = smem;
    int tid = threadIdx.x;
    #pragma unroll
    for (int ld = 0; ld < 8; ld++) {
        int id = tid + ld * 256;
        int r = id >> 5;
        int c = (id & 31) * 4;
        int row = n0 + r;
        if (row < M) {
            float4 v = *(float4*)&sC[r * LDC + c];
            float4 bb = *(const float4*)&b[c];
            float4 ov;
            ov.x = fmaxf(v.x + bb.x, 0.0f);
            ov.y = fmaxf(v.y + bb.y, 0.0f);
            ov.z = fmaxf(v.z + bb.z, 0.0f);
            ov.w = fmaxf(v.w + bb.w, 0.0f);
            *(float4*)&y[(size_t)row * HD + c] = ov;
        }
    }
}

// final: emb = xj@Wjf + bjf; scores = emb@q; K=128, N=128
__global__ __launch_bounds__(256) void k_final_t(
    const float* __restrict__ x, const float* __restrict__ W,
    const float* __restrict__ b, const float* __restrict__ q,
    float* __restrict__ scores, float* __restrict__ emb, int M) {
    extern __shared__ float smem[];
    int n0 = blockIdx.x * 64;
    gemm_tile<HD, HD>(x, W, smem, n0, M);
    constexpr int LDC = HD + 8;
    float* sC = smem;
    int tid = threadIdx.x, w = tid >> 5, lane = tid & 31;
    float4 b4 = *(const float4*)&b[lane * 4];
    float4 q4 = *(const float4*)&q[lane * 4];
    #pragma unroll
    for (int r8 = 0; r8 < 8; r8++) {
        int r = w * 8 + r8;
        int row = n0 + r;
        float4 v = *(float4*)&sC[r * LDC + lane * 4];
        v.x += b4.x; v.y += b4.y; v.z += b4.z; v.w += b4.w;
        float p = v.x * q4.x + v.y * q4.y + v.z * q4.z + v.w * q4.w;
        #pragma unroll
        for (int o = 16; o; o >>= 1) p += __shfl_xor_sync(0xFFFFFFFFu, p, o);
        if (row < M) {
            *(float4*)&emb[(size_t)row * HD + lane * 4] = v;
            if (lane == 0) scores[row] = p;
        }
    }
}

// ======================= irregular kernels =======================

// all three relations' alpha_d in one launch
__global__ void k_alpha3(const float* __restrict__ xs, const float* __restrict__ xj,
                         const float* __restrict__ vd,  // layer base: 3*[HD][2]
                         float* __restrict__ ad0, float* __restrict__ ad1,
                         float* __restrict__ ad2) {
    int b = blockIdx.x;
    const float* x; const float* v; float* ad; int N; int row0;
    if (b < 1500)      { x = xs; v = vd + 0 * HD * 2; ad = ad0; N = NS; row0 = b * 8; }
    else if (b < 3000) { x = xs; v = vd + 2 * HD * 2; ad = ad1; N = NS; row0 = (b - 1500) * 8; }
    else               { x = xj; v = vd + 1 * HD * 2; ad = ad2; N = NJ; row0 = (b - 3000) * 8; }
    int wp = threadIdx.x >> 5, lane = threadIdx.x & 31;
    int row = row0 + wp;
    if (row >= N) return;
    float a0 = 0.0f, a1 = 0.0f;
    for (int k = lane; k < HD; k += 32) {
        float xv = x[row * HD + k];
        float2 vv = *(const float2*)&v[k * 2];
        a0 += xv * vv.x;
        a1 += xv * vv.y;
    }
    #pragma unroll
    for (int o = 16; o; o >>= 1) {
        a0 += __shfl_xor_sync(0xFFFFFFFFu, a0, o);
        a1 += __shfl_xor_sync(0xFFFFFFFFu, a1, o);
    }
    if (lane == 0) *(float2*)&ad[row * 2] = make_float2(a0, a1);
}

// vd[lr][k][h] = sum_c Wd[lr][k][h*128+c] * a_d[lr][h][c]
__global__ void k_prep(const float* __restrict__ Wd, const float* __restrict__ adv,
                       float* __restrict__ vd) {
    int lr = blockIdx.x;
    int k = threadIdx.x >> 1, h = threadIdx.x & 1;
    const float* wrow = Wd + ((size_t)lr * HD + k) * HH + h * HD;
    const float* arow = adv + (lr * 2 + h) * HD;
    float s = 0.0f;
    for (int c = 0; c < HD; c++) s += wrow[c] * arow[c];
    vd[lr * (HD * 2) + k * 2 + h] = s;
}

// combined degree count over all 3 relations
__global__ void k_count_all(const int* __restrict__ jsd, const int* __restrict__ sjd,
                            const int* __restrict__ ssd, int* __restrict__ deg) {
    int t = blockIdx.x * blockDim.x + threadIdx.x;
    if (t >= TOTE) return;
    int di;
    if (t < EJS) di = jsd[t];
    else if (t < EJS + ESJ) di = NS + sjd[t - EJS];
    else {
        int i = t - EJS - ESJ;
        di = NS + NJ + ((i < ESS) ? ssd[i] : (i - ESS));
    }
    atomicAdd(&deg[di], 1);
}

// combined scatter; stores SRC node id directly in list
__global__ void k_scatter_all(const int* __restrict__ jsd, const int* __restrict__ jss,
                              const int* __restrict__ sjd, const int* __restrict__ sjs,
                              const int* __restrict__ ssd, const int* __restrict__ sss,
                              int* __restrict__ cur, int* __restrict__ list) {
    int t = blockIdx.x * blockDim.x + threadIdx.x;
    if (t >= TOTE) return;
    int di, sv;
    if (t < EJS) { di = jsd[t]; sv = jss[t]; }
    else if (t < EJS + ESJ) { int i = t - EJS; di = NS + sjd[i]; sv = sjs[i]; }
    else {
        int i = t - EJS - ESJ;
        if (i < ESS) { di = NS + NJ + ssd[i]; sv = sss[i]; }
        else { di = NS + NJ + (i - ESS); sv = i - ESS; }
    }
    int pos = atomicAdd(&cur[di], 1);
    list[pos] = sv;
}

// multi-block scan: phase A
__global__ void k_scanA(const int* __restrict__ deg, int* __restrict__ off,
                        int* __restrict__ part) {
    int chunk = blockIdx.x;
    int i = chunk * 1024 + threadIdx.x;
    int v = (i < NDTOT) ? deg[i] : 0;
    int lane = threadIdx.x & 31, wid = threadIdx.x >> 5;
    int incl = v;
    #pragma unroll
    for (int o = 1; o < 32; o <<= 1) {
        int t = __shfl_up_sync(0xFFFFFFFFu, incl, o);
        if (lane >= o) incl += t;
    }
    __shared__ int ws[32];
    if (lane == 31) ws[wid] = incl;
    __syncthreads();
    if (wid == 0) {
        int inc2 = ws[lane];
        #pragma unroll
        for (int o = 1; o < 32; o <<= 1) {
            int u = __shfl_up_sync(0xFFFFFFFFu, inc2, o);
            if (lane >= o) inc2 += u;
        }
        ws[lane] = inc2;
    }
    __syncthreads();
    int base = (wid > 0) ? ws[wid - 1] : 0;
    if (i < NDTOT) off[i] = base + incl - v;
    if (threadIdx.x == 1023) part[chunk] = base + incl;
}

// phase B: exclusive scan of NCHUNK partials (1 block, 64 threads)
__global__ void k_scanB(int* __restrict__ part) {
    int t = threadIdx.x;
    int lane = t & 31, w = t >> 5;
    int v = (t < NCHUNK) ? part[t] : 0;
    int incl = v;
    #pragma unroll
    for (int o = 1; o < 32; o <<= 1) {
        int u = __shfl_up_sync(0xFFFFFFFFu, incl, o);
        if (lane >= o) incl += u;
    }
    __shared__ int wsum[2];
    if (lane == 31) wsum[w] = incl;
    __syncthreads();
    if (w == 1) incl += wsum[0];
    if (t < NCHUNK) part[t] = incl - v;
}

// phase C: add chunk bases, seed cur
__global__ void k_scanC(int* __restrict__ off, int* __restrict__ cur,
                        const int* __restrict__ part) {
    int chunk = blockIdx.x;
    int i = chunk * 1024 + threadIdx.x;
    if (i < NDTOT) {
        int v = off[i] + part[chunk];
        off[i] = v;
        cur[i] = v;
    }
}

// fused per-dst GAT softmax + aggregation. 256 threads per dst node.
__global__ __launch_bounds__(256) void k_agg_f(
    const int* __restrict__ deg, const int* __restrict__ off,
    const int* __restrict__ list, const float* __restrict__ asb,
    const float* __restrict__ adb, const float* __restrict__ hs,
    const float* __restrict__ bias, float* __restrict__ out, int accum) {
    __shared__ float se0[AGG_CAP], se1[AGG_CAP];
    __shared__ int slist[AGG_CAP];
    __shared__ float4 racc[256];
    __shared__ float r0[8], r1[8];
    int d = blockIdx.x;
    int dg = deg[d], st = off[d];
    int tid = threadIdx.x, lane = tid & 31, w = tid >> 5;
    float2 ad = *(const float2*)&adb[2 * d];
    float si0, si1;
    int grp = tid >> 6, comp = (tid & 63) << 2;
    int hh = comp >> 7;

    if (dg <= AGG_CAP) {
        // pass 1: gather alpha, compute e, cache, block max
        float m0 = -INFINITY, m1 = -INFINITY;
        for (int i = tid; i < dg; i += 256) {
            int s = list[st + i];
            slist[i] = s;
            float2 a = *(const float2*)&asb[2 * s];
            float e0 = a.x + ad.x; e0 = (e0 > 0.f) ? e0 : NEG * e0;
            float e1 = a.y + ad.y; e1 = (e1 > 0.f) ? e1 : NEG * e1;
            se0[i] = e0; se1[i] = e1;
            m0 = fmaxf(m0, e0); m1 = fmaxf(m1, e1);
        }
        #pragma unroll
        for (int o = 16; o; o >>= 1) {
            m0 = fmaxf(m0, __shfl_xor_sync(0xFFFFFFFFu, m0, o));
            m1 = fmaxf(m1, __shfl_xor_sync(0xFFFFFFFFu, m1, o));
        }
        if (lane == 0) { r0[w] = m0; r1[w] = m1; }
        __syncthreads();
        float mm0 = r0[0], mm1 = r1[0];
        #pragma unroll
        for (int k = 1; k < 8; k++) { mm0 = fmaxf(mm0, r0[k]); mm1 = fmaxf(mm1, r1[k]); }
        __syncthreads();
        // pass 2: exp + denominator (weights overwrite se)
        float d0 = 0.f, d1 = 0.f;
        for (int i = tid; i < dg; i += 256) {
            float w0 = __expf(se0[i] - mm0); se0[i] = w0; d0 += w0;
            float w1 = __expf(se1[i] - mm1); se1[i] = w1; d1 += w1;
        }
        #pragma unroll
        for (int o = 16; o; o >>= 1) {
            d0 += __shfl_xor_sync(0xFFFFFFFFu, d0, o);
            d1 += __shfl_xor_sync(0xFFFFFFFFu, d1, o);
        }
        if (lane == 0) { r0[w] = d0; r1[w] = d1; }
        __syncthreads();
        float den0 = 0.f, den1 = 0.f;
        #pragma unroll
        for (int k = 0; k < 8; k++) { den0 += r0[k]; den1 += r1[k]; }
        si0 = 1.f / (den0 + 1e-16f);
        si1 = 1.f / (den1 + 1e-16f);
        // pass 3: float4 gather, 4 edges/iter per block, 2x unrolled
        const float* sw = hh ? se1 : se0;
        float4 acc = make_float4(0.f, 0.f, 0.f, 0.f);
        int i = grp;
        for (; i + 4 < dg; i += 8) {
            int sA = slist[i], sB = slist[i + 4];
            float wA = sw[i], wB = sw[i + 4];
            float4 vA = *(const float4*)&hs[(size_t)sA * HH + comp];
            float4 vB = *(const float4*)&hs[(size_t)sB * HH + comp];
            acc.x += wA * vA.x + wB * vB.x;
            acc.y += wA * vA.y + wB * vB.y;
            acc.z += wA * vA.z + wB * vB.z;
            acc.w += wA * vA.w + wB * vB.w;
        }
        if (i < dg) {
            int sA = slist[i];
            float wA = sw[i];
            float4 vA = *(const float4*)&hs[(size_t)sA * HH + comp];
            acc.x += wA * vA.x; acc.y += wA * vA.y;
            acc.z += wA * vA.z; acc.w += wA * vA.w;
        }
        racc[tid] = acc;
    } else {
        // fallback: recompute (no smem cache) — not expected on this data
        float m0 = -INFINITY, m1 = -INFINITY;
        for (int i = tid; i < dg; i += 256) {
            int s = list[st + i];
            float2 a = *(const float2*)&asb[2 * s];
            float e0 = a.x + ad.x; e0 = (e0 > 0.f) ? e0 : NEG * e0;
            float e1 = a.y + ad.y; e1 = (e1 > 0.f) ? e1 : NEG * e1;
            m0 = fmaxf(m0, e0); m1 = fmaxf(m1, e1);
        }
        #pragma unroll
        for (int o = 16; o; o >>= 1) {
            m0 = fmaxf(m0, __shfl_xor_sync(0xFFFFFFFFu, m0, o));
            m1 = fmaxf(m1, __shfl_xor_sync(0xFFFFFFFFu, m1, o));
        }
        if (lane == 0) { r0[w] = m0; r1[w] = m1; }
        __syncthreads();
        float mm0 = r0[0], mm1 = r1[0];
        #pragma unroll
        for (int k = 1; k < 8; k++) { mm0 = fmaxf(mm0, r0[k]); mm1 = fmaxf(mm1, r1[k]); }
        __syncthreads();
        float d0 = 0.f, d1 = 0.f;
        for (int i = tid; i < dg; i += 256) {
            int s = list[st + i];
            float2 a = *(const float2*)&asb[2 * s];
            float e0 = a.x + ad.x; e0 = (e0 > 0.f) ? e0 : NEG * e0;
            float e1 = a.y + ad.y; e1 = (e1 > 0.f) ? e1 : NEG * e1;
            d0 += __expf(e0 - mm0);
            d1 += __expf(e1 - mm1);
        }
        #pragma unroll
        for (int o = 16; o; o >>= 1) {
            d0 += __shfl_xor_sync(0xFFFFFFFFu, d0, o);
            d1 += __shfl_xor_sync(0xFFFFFFFFu, d1, o);
        }
        if (lane == 0) { r0[w] = d0; r1[w] = d1; }
        __syncthreads();
        float den0 = 0.f, den1 = 0.f;
        #pragma unroll
        for (int k = 0; k < 8; k++) { den0 += r0[k]; den1 += r1[k]; }
        si0 = 1.f / (den0 + 1e-16f);
        si1 = 1.f / (den1 + 1e-16f);
        float adh = hh ? ad.y : ad.x;
        float mmh = hh ? mm1 : mm0;
        float4 acc = make_float4(0.f, 0.f, 0.f, 0.f);
        for (int i = grp; i < dg; i += 4) {
            int s = list[st + i];
            float av = asb[2 * s + hh];
            float e = av + adh; e = (e > 0.f) ? e : NEG * e;
            float wA = __expf(e - mmh);
            float4 vA = *(const float4*)&hs[(size_t)s * HH + comp];
            acc.x += wA * vA.x; acc.y += wA * vA.y;
            acc.z += wA * vA.z; acc.w += wA * vA.w;
        }
        racc[tid] = acc;
    }
    __syncthreads();
    // cross-group reduce + scale + bias + write (64 threads, float4 each)
    if (tid < 64) {
        float4 a4 = racc[tid], b4 = racc[tid + 64];
        float4 c4 = racc[tid + 128], d4 = racc[tid + 192];
        int cmp = tid << 2;
        float si = (cmp >= 128) ? si1 : si0;
        float4 bb = *(const float4*)&bias[cmp];
        float4 o;
        o.x = (a4.x + b4.x + c4.x + d4.x) * si + bb.x;
        o.y = (a4.y + b4.y + c4.y + d4.y) * si + bb.y;
        o.z = (a4.z + b4.z + c4.z + d4.z) * si + bb.z;
        o.w = (a4.w + b4.w + c4.w + d4.w) * si + bb.w;
        size_t oi = (size_t)d * HH + cmp;
        if (accum) {
            float4 p = *(float4*)&out[oi];
            o.x += p.x; o.y += p.y; o.z += p.z; o.w += p.w;
        }
        *(float4*)&out[oi] = o;
    }
}

// q = query @ Wq + bq
__global__ void k_q(const float* __restrict__ query, const float* __restrict__ Wq,
                    const float* __restrict__ bq, float* __restrict__ q) {
    int c = threadIdx.x;
    float acc = bq[c];
    for (int k = 0; k < SB; k++) acc += query[k] * Wq[k * HD + c];
    q[c] = acc;
}

// ---------------- host launch ----------------
static inline int cdiv(int a, int b) { return (a + b - 1) / b; }

extern "C" void kernel_launch(void* const* d_in, const int* in_sizes, int n_in,
                              void* d_out, int out_size) {
    const float* x_job   = (const float*)d_in[0];
    const float* x_skill = (const float*)d_in[1];
    const int* js_src = (const int*)d_in[2];
    const int* js_dst = (const int*)d_in[3];
    const int* sj_src = (const int*)d_in[4];
    const int* sj_dst = (const int*)d_in[5];
    const int* ss_src = (const int*)d_in[6];
    const int* ss_dst = (const int*)d_in[7];
    const float* query    = (const float*)d_in[8];
    const float* W0_job   = (const float*)d_in[9];
    const float* b0_job   = (const float*)d_in[10];
    const float* g0_job   = (const float*)d_in[11];
    const float* be0_job  = (const float*)d_in[12];
    const float* W0_skill = (const float*)d_in[13];
    const float* b0_skill = (const float*)d_in[14];
    const float* g0_skill = (const float*)d_in[15];
    const float* be0_skill= (const float*)d_in[16];
    const float* gat_Ws = (const float*)d_in[17];
    const float* gat_Wd = (const float*)d_in[18];
    const float* gat_as = (const float*)d_in[19];
    const float* gat_ad = (const float*)d_in[20];
    const float* gat_b  = (const float*)d_in[21];
    const float* inter_W= (const float*)d_in[22];
    const float* inter_b= (const float*)d_in[23];
    const float* Wjf = (const float*)d_in[24];
    const float* bjf = (const float*)d_in[25];
    const float* Wq  = (const float*)d_in[26];
    const float* bq  = (const float*)d_in[27];

    float* out = (float*)d_out;
    float* out_scores = out;
    float* out_emb = out + NJ;
    float* out_q = out + NJ + (size_t)NJ * HD;

    float *xj0, *xj1, *xs0, *xs1, *hsJ, *hsS1, *hsS2, *oJ, *oS;
    float *asbJ, *asbS1, *asbS2, *adb0, *adb1, *adb2, *vd;
    int *part, *deg, *off, *cur, *list;
    cudaGetSymbolAddress((void**)&xj0, g_xj0);
    cudaGetSymbolAddress((void**)&xj1, g_xj1);
    cudaGetSymbolAddress((void**)&xs0, g_xs0);
    cudaGetSymbolAddress((void**)&xs1, g_xs1);
    cudaGetSymbolAddress((void**)&hsJ, g_hsJ);
    cudaGetSymbolAddress((void**)&hsS1, g_hsS1);
    cudaGetSymbolAddress((void**)&hsS2, g_hsS2);
    cudaGetSymbolAddress((void**)&oJ, g_oJ);
    cudaGetSymbolAddress((void**)&oS, g_oS);
    cudaGetSymbolAddress((void**)&asbJ, g_asbJ);
    cudaGetSymbolAddress((void**)&asbS1, g_asbS1);
    cudaGetSymbolAddress((void**)&asbS2, g_asbS2);
    cudaGetSymbolAddress((void**)&adb0, g_adb0);
    cudaGetSymbolAddress((void**)&adb1, g_adb1);
    cudaGetSymbolAddress((void**)&adb2, g_adb2);
    cudaGetSymbolAddress((void**)&vd, g_vd);
    cudaGetSymbolAddress((void**)&part, g_part);
    cudaGetSymbolAddress((void**)&deg, g_deg);
    cudaGetSymbolAddress((void**)&off, g_off);
    cudaGetSymbolAddress((void**)&cur, g_cur);
    cudaGetSymbolAddress((void**)&list, g_list);

    const int SM_N128 = (64 * (HD + 8)) * 4;
    const int SM_N256 = (64 * (HH + 8)) * 4;
    cudaFuncSetAttribute(k_lin0_t,    cudaFuncAttributeMaxDynamicSharedMemorySize, SM_N128);
    cudaFuncSetAttribute(k_inter_t,   cudaFuncAttributeMaxDynamicSharedMemorySize, SM_N128);
    cudaFuncSetAttribute(k_final_t,   cudaFuncAttributeMaxDynamicSharedMemorySize, SM_N128);
    cudaFuncSetAttribute(k_gat_src_t, cudaFuncAttributeMaxDynamicSharedMemorySize, SM_N256);

    const int GJ = cdiv(NJ, 64);   // 469
    const int GS = cdiv(NS, 64);   // 188

    float* xj_cur = xj0; float* xs_cur = xs0;
    float* xj_nxt = xj1; float* xs_nxt = xs1;

    // ---- setup phase (ordered so launch #6 is the big GEMM for ncu) ----
    cudaMemsetAsync(deg, 0, NDTOT * sizeof(int));
    k_lin0_t<<<GJ, 256, SM_N128>>>(x_job, W0_job, b0_job, g0_job, be0_job, xj0, NJ);
    k_lin0_t<<<GS, 256, SM_N128>>>(x_skill, W0_skill, b0_skill, g0_skill, be0_skill, xs0, NS);
    k_prep<<<6, 256>>>(gat_Wd, gat_ad, vd);
    k_count_all<<<cdiv(TOTE, 256), 256>>>(js_dst, sj_dst, ss_dst, deg);
    // layer-0 js gat_src (independent of CSR) — candidate for the ncu sample
    k_gat_src_t<<<GJ, 256, SM_N256>>>(xj_cur, gat_Ws + (size_t)0 * HD * HH,
                                      gat_as + 0 * 2 * HD, hsJ, asbJ, NJ);
    k_scanA<<<NCHUNK, 1024>>>(deg, off, part);
    k_scanB<<<1, 64>>>(part);
    k_scanC<<<NCHUNK, 1024>>>(off, cur, part);
    k_scatter_all<<<cdiv(TOTE, 256), 256>>>(js_dst, js_src, sj_dst, sj_src,
                                            ss_dst, ss_src, cur, list);

    for (int l = 0; l < 2; l++) {
        int lr0 = l * 3 + 0, lr1 = l * 3 + 1, lr2 = l * 3 + 2;
        if (l > 0) {
            k_gat_src_t<<<GJ, 256, SM_N256>>>(xj_cur, gat_Ws + (size_t)lr0 * HD * HH,
                                              gat_as + lr0 * 2 * HD, hsJ, asbJ, NJ);
        }
        k_gat_src_t<<<GS, 256, SM_N256>>>(xs_cur, gat_Ws + (size_t)lr2 * HD * HH,
                                          gat_as + lr2 * 2 * HD, hsS1, asbS1, NS);
        k_gat_src_t<<<GS, 256, SM_N256>>>(xs_cur, gat_Ws + (size_t)lr1 * HD * HH,
                                          gat_as + lr1 * 2 * HD, hsS2, asbS2, NS);
        k_alpha3<<<6750, 256>>>(xs_cur, xj_cur, vd + (size_t)l * 3 * HD * 2,
                                adb0, adb1, adb2);
        // js: jobs -> skills (deg base 0), init oS
        k_agg_f<<<NS, 256>>>(deg, off, list, asbJ, adb0, hsJ,
                             gat_b + lr0 * HH, oS, 0);
        // ss: skills -> skills (+loops, deg base NS+NJ), accumulate oS
        k_agg_f<<<NS, 256>>>(deg + NS + NJ, off + NS + NJ, list, asbS1, adb1, hsS1,
                             gat_b + lr2 * HH, oS, 1);
        // sj: skills -> jobs (deg base NS), init oJ
        k_agg_f<<<NJ, 256>>>(deg + NS, off + NS, list, asbS2, adb2, hsS2,
                             gat_b + lr1 * HH, oJ, 0);
        // inter linears
        k_inter_t<<<GJ, 256, SM_N128>>>(oJ, inter_W + (size_t)(l * 2 + 0) * HH * HD,
                                        inter_b + (l * 2 + 0) * HD, xj_nxt, NJ);
        k_inter_t<<<GS, 256, SM_N128>>>(oS, inter_W + (size_t)(l * 2 + 1) * HH * HD,
                                        inter_b + (l * 2 + 1) * HD, xs_nxt, NS);
        float* t;
        t = xj_cur; xj_cur = xj_nxt; xj_nxt = t;
        t = xs_cur; xs_cur = xs_nxt; xs_nxt = t;
    }

    // final projection + query + scores
    k_q<<<1, 128>>>(query, Wq, bq, out_q);
    k_final_t<<<GJ, 256, SM_N128>>>(xj_cur, Wjf, bjf, out_q, out_scores, out_emb, NJ);
}